// round 1
// baseline (speedup 1.0000x reference)
#include <cuda_runtime.h>
#include <math_constants.h>

// Problem constants (fixed by the reference: B=4, S=2048, D_IN=D_OUT=1024)
constexpr int BATCH = 4;
constexpr int SEQ   = 2048;
constexpr int DIM   = 1024;
constexpr int MTOT  = BATCH * SEQ;   // 8192

// Scratch in __device__ globals (no allocation allowed in kernel_launch)
__device__ float g_Q[(size_t)MTOT * DIM];           // 32 MB
__device__ float g_K[(size_t)MTOT * DIM];           // 32 MB
__device__ float g_V[(size_t)MTOT * DIM];           // 32 MB
__device__ float g_S[(size_t)BATCH * SEQ * SEQ];    // 64 MB (scores -> attn probs)
__device__ float g_O[(size_t)MTOT * DIM];           // 32 MB (attn @ V)

// ---------------------------------------------------------------------------
// Tiled fp32 GEMM: C = alpha * A @ op(B)  (+ bias broadcast over rows)
//   A: M x K row-major
//   B: K x N row-major (TRANS_B=false)  or  N x K row-major (TRANS_B=true)
//   C: M x N row-major
// 128x128 block tile, BK=16, 256 threads, 8x8 per-thread microkernel.
// All dims must be multiples of the tile sizes (true for this problem).
// blockIdx.z selects batch via the given element strides.
// ---------------------------------------------------------------------------
#define BM 128
#define BN 128
#define BKK 16
#define TM 8
#define TN 8

template<bool TRANS_B, bool ADD_BIAS>
__global__ __launch_bounds__(256, 2)
void sgemm_kernel(const float* __restrict__ A,
                  const float* __restrict__ B,
                  const float* __restrict__ bias,
                  float* __restrict__ C,
                  int M, int N, int K, float alpha,
                  long long strideA, long long strideB, long long strideC)
{
    A += (long long)blockIdx.z * strideA;
    B += (long long)blockIdx.z * strideB;
    C += (long long)blockIdx.z * strideC;

    __shared__ float As[BKK][BM];
    __shared__ float Bs[BKK][BN];

    const int tid = threadIdx.x;
    const int rowBase = blockIdx.y * BM;
    const int colBase = blockIdx.x * BN;

    const int ty = tid >> 4;   // 0..15
    const int tx = tid & 15;   // 0..15

    float acc[TM][TN];
    #pragma unroll
    for (int i = 0; i < TM; i++)
        #pragma unroll
        for (int j = 0; j < TN; j++)
            acc[i][j] = 0.0f;

    for (int k0 = 0; k0 < K; k0 += BKK) {
        // ---- load A tile: 128 rows x 16 cols (row-major, lda = K) ----
        #pragma unroll
        for (int l = 0; l < 2; l++) {
            int idx = tid + l * 256;          // float4 index, 0..511
            int r   = idx >> 2;               // 0..127
            int c4  = (idx & 3) << 2;         // 0,4,8,12
            float4 v = *reinterpret_cast<const float4*>(
                A + (long long)(rowBase + r) * K + k0 + c4);
            As[c4 + 0][r] = v.x;
            As[c4 + 1][r] = v.y;
            As[c4 + 2][r] = v.z;
            As[c4 + 3][r] = v.w;
        }
        // ---- load B tile ----
        if (TRANS_B) {
            // B is N x K row-major; tile = 128 B-rows x 16 K-cols
            #pragma unroll
            for (int l = 0; l < 2; l++) {
                int idx = tid + l * 256;
                int r   = idx >> 2;
                int c4  = (idx & 3) << 2;
                float4 v = *reinterpret_cast<const float4*>(
                    B + (long long)(colBase + r) * K + k0 + c4);
                Bs[c4 + 0][r] = v.x;
                Bs[c4 + 1][r] = v.y;
                Bs[c4 + 2][r] = v.z;
                Bs[c4 + 3][r] = v.w;
            }
        } else {
            // B is K x N row-major; tile = 16 K-rows x 128 N-cols
            #pragma unroll
            for (int l = 0; l < 2; l++) {
                int idx = tid + l * 256;      // float4 index
                int r   = idx >> 5;           // 0..15
                int c   = (idx & 31) << 2;    // 0..124 step 4
                *reinterpret_cast<float4*>(&Bs[r][c]) =
                    *reinterpret_cast<const float4*>(
                        B + (long long)(k0 + r) * N + colBase + c);
            }
        }
        __syncthreads();

        // ---- 8x8 microkernel over BK ----
        #pragma unroll
        for (int k = 0; k < BKK; k++) {
            float ra[TM], rb[TN];
            *reinterpret_cast<float4*>(&ra[0]) = *reinterpret_cast<const float4*>(&As[k][ty * TM + 0]);
            *reinterpret_cast<float4*>(&ra[4]) = *reinterpret_cast<const float4*>(&As[k][ty * TM + 4]);
            *reinterpret_cast<float4*>(&rb[0]) = *reinterpret_cast<const float4*>(&Bs[k][tx * TN + 0]);
            *reinterpret_cast<float4*>(&rb[4]) = *reinterpret_cast<const float4*>(&Bs[k][tx * TN + 4]);
            #pragma unroll
            for (int i = 0; i < TM; i++)
                #pragma unroll
                for (int j = 0; j < TN; j++)
                    acc[i][j] = fmaf(ra[i], rb[j], acc[i][j]);
        }
        __syncthreads();
    }

    // ---- epilogue ----
    #pragma unroll
    for (int i = 0; i < TM; i++) {
        int row = rowBase + ty * TM + i;
        #pragma unroll
        for (int j = 0; j < TN; j += 4) {
            int col = colBase + tx * TN + j;
            float4 v;
            v.x = acc[i][j + 0] * alpha;
            v.y = acc[i][j + 1] * alpha;
            v.z = acc[i][j + 2] * alpha;
            v.w = acc[i][j + 3] * alpha;
            if (ADD_BIAS) {
                v.x += bias[col + 0];
                v.y += bias[col + 1];
                v.z += bias[col + 2];
                v.w += bias[col + 3];
            }
            *reinterpret_cast<float4*>(C + (long long)row * N + col) = v;
        }
    }
}

// ---------------------------------------------------------------------------
// Row-wise softmax over SEQ=2048 columns. One 256-thread block per row.
// ---------------------------------------------------------------------------
__global__ __launch_bounds__(256)
void softmax_rows_kernel(float* __restrict__ S)
{
    float* row = S + (long long)blockIdx.x * SEQ;
    const int tid = threadIdx.x;

    float v[8];
    float m = -CUDART_INF_F;
    #pragma unroll
    for (int i = 0; i < 8; i++) {
        v[i] = row[tid + i * 256];
        m = fmaxf(m, v[i]);
    }

    __shared__ float red[256];
    red[tid] = m;
    __syncthreads();
    #pragma unroll
    for (int s = 128; s > 0; s >>= 1) {
        if (tid < s) red[tid] = fmaxf(red[tid], red[tid + s]);
        __syncthreads();
    }
    m = red[0];
    __syncthreads();

    float sum = 0.0f;
    #pragma unroll
    for (int i = 0; i < 8; i++) {
        v[i] = __expf(v[i] - m);
        sum += v[i];
    }
    red[tid] = sum;
    __syncthreads();
    #pragma unroll
    for (int s = 128; s > 0; s >>= 1) {
        if (tid < s) red[tid] += red[tid + s];
        __syncthreads();
    }
    float inv = 1.0f / red[0];

    #pragma unroll
    for (int i = 0; i < 8; i++)
        row[tid + i * 256] = v[i] * inv;
}

// ---------------------------------------------------------------------------
// Launch
// Inputs (metadata order): inputs[B,S,D], Wq[D,D], Wk[D,D], Wv[D,D], Wo[D,D], bo[D]
// Output: float32 [B,S,D]
// ---------------------------------------------------------------------------
extern "C" void kernel_launch(void* const* d_in, const int* in_sizes, int n_in,
                              void* d_out, int out_size)
{
    const float* X  = (const float*)d_in[0];
    const float* Wq = (const float*)d_in[1];
    const float* Wk = (const float*)d_in[2];
    const float* Wv = (const float*)d_in[3];
    const float* Wo = (const float*)d_in[4];
    const float* bo = (const float*)d_in[5];
    float* out = (float*)d_out;

    float *Q, *K, *V, *S, *O;
    cudaGetSymbolAddress((void**)&Q, g_Q);
    cudaGetSymbolAddress((void**)&K, g_K);
    cudaGetSymbolAddress((void**)&V, g_V);
    cudaGetSymbolAddress((void**)&S, g_S);
    cudaGetSymbolAddress((void**)&O, g_O);

    dim3 block(256);
    const float scale = 1.0f / 32.0f;   // 1/sqrt(1024)

    // 1) QKV projections: [8192,1024] = X @ W  (NN, K=1024)
    {
        dim3 grid(DIM / BN, MTOT / BM, 1);
        sgemm_kernel<false, false><<<grid, block>>>(X, Wq, nullptr, Q,
            MTOT, DIM, DIM, 1.0f, 0, 0, 0);
        sgemm_kernel<false, false><<<grid, block>>>(X, Wk, nullptr, K,
            MTOT, DIM, DIM, 1.0f, 0, 0, 0);
        sgemm_kernel<false, false><<<grid, block>>>(X, Wv, nullptr, V,
            MTOT, DIM, DIM, 1.0f, 0, 0, 0);
    }

    // 2) scores: per batch, S_b = (Q_b @ K_b^T) * scale   (NT, M=N=2048, K=1024)
    {
        dim3 grid(SEQ / BN, SEQ / BM, BATCH);
        sgemm_kernel<true, false><<<grid, block>>>(Q, K, nullptr, S,
            SEQ, SEQ, DIM, scale,
            (long long)SEQ * DIM, (long long)SEQ * DIM, (long long)SEQ * SEQ);
    }

    // 3) row-wise softmax over all B*S rows
    softmax_rows_kernel<<<BATCH * SEQ, block>>>(S);

    // 4) O_b = P_b @ V_b   (NN, M=2048, N=1024, K=2048)
    {
        dim3 grid(DIM / BN, SEQ / BM, BATCH);
        sgemm_kernel<false, false><<<grid, block>>>(S, V, nullptr, O,
            SEQ, DIM, SEQ, 1.0f,
            (long long)SEQ * SEQ, (long long)SEQ * DIM, (long long)SEQ * DIM);
    }

    // 5) out = O @ Wo + bo   (NN, M=8192, N=1024, K=1024, bias)
    {
        dim3 grid(DIM / BN, MTOT / BM, 1);
        sgemm_kernel<false, true><<<grid, block>>>(O, Wo, bo, out,
            MTOT, DIM, DIM, 1.0f, 0, 0, 0);
    }
}